// round 1
// baseline (speedup 1.0000x reference)
#include <cuda_runtime.h>
#include <math.h>

// ---------------- scratch (device globals; no allocations allowed) ----------
// xz: input-to-gate conv for all B*T=64 images: (64, 64, 64, 256) floats
__device__ float g_xz[(size_t)64 * 4096 * 256];   // 268 MB
// z: recurrent conv output for one timestep: (4, 64, 64, 256)
__device__ float g_z[(size_t)4 * 4096 * 256];     // 16.8 MB
// LSTM state: (4, 64, 64, 64)
__device__ float g_h[(size_t)4 * 4096 * 64];
__device__ float g_c[(size_t)4 * 4096 * 64];

// ---------------- zero-init state ------------------------------------------
__global__ void zero_state_kernel(float* __restrict__ h, float* __restrict__ c, int n) {
    int i = blockIdx.x * blockDim.x + threadIdx.x;
    if (i < n) { h[i] = 0.f; c[i] = 0.f; }
}

// ---------------- implicit-GEMM conv ---------------------------------------
// Z[m, co] = sum_{ky,kx,ci} X[n, oy*S+ky-PAD, ox*S+kx-PAD, ci] * W[ky,kx,ci,co]
// m = n*HOUT*HOUT + oy*HOUT + ox.  N(co) = 256 always.
// BM=128, BN=128, BK=32; 256 threads; 8x8 micro-tile per thread.
// K-chunk of 32 lies within a single (ky,kx) tap since CIN % 32 == 0.
template<int STRIDE, int PAD, int CIN, int HIN, int HOUT>
__global__ __launch_bounds__(256, 2)
void conv_gemm_kernel(const float* __restrict__ X, const float* __restrict__ Wf,
                      float* __restrict__ Z) {
    __shared__ float As[32][128];
    __shared__ float Bs[32][128];

    const int t = threadIdx.x;
    const int mBase  = blockIdx.x * 128;
    const int coBase = blockIdx.y * 128;

    // ---- A-load geometry (fixed per thread)
    const int rowA  = t & 127;          // pixel row within tile
    const int halfA = t >> 7;           // 0/1 -> ci sub-offset 16*halfA
    const int m   = mBase + rowA;
    const int n   = m / (HOUT * HOUT);
    const int rem = m % (HOUT * HOUT);
    const int oy  = rem / HOUT;
    const int ox  = rem % HOUT;

    // ---- B-load geometry
    const int c4  = t & 31;             // float4 column
    const int kB0 = t >> 5;             // rows kB0 + r*8

    // ---- compute geometry
    const int tx = t & 15;
    const int ty = t >> 4;

    float acc[8][8];
#pragma unroll
    for (int i = 0; i < 8; i++)
#pragma unroll
        for (int j = 0; j < 8; j++) acc[i][j] = 0.f;

    const int KCHUNKS = (9 * CIN) / 32;

    for (int ch = 0; ch < KCHUNKS; ++ch) {
        const int kBase = ch * 32;
        const int tap   = kBase / CIN;       // 0..8
        const int ciOff = kBase % CIN;       // 0 or 32
        const int ky = tap / 3, kx = tap % 3;

        // ---- load A tile (128 pixels x 32 k)
        {
            const int iy = oy * STRIDE + ky - PAD;
            const int ix = ox * STRIDE + kx - PAD;
            const bool ok = (iy >= 0) & (iy < HIN) & (ix >= 0) & (ix < HIN);
            const float4* src = (const float4*)(X +
                (((size_t)n * HIN + iy) * HIN + ix) * CIN + ciOff + halfA * 16);
#pragma unroll
            for (int j = 0; j < 4; j++) {
                float4 v = ok ? src[j] : make_float4(0.f, 0.f, 0.f, 0.f);
                const int kk = halfA * 16 + j * 4;
                As[kk + 0][rowA] = v.x;
                As[kk + 1][rowA] = v.y;
                As[kk + 2][rowA] = v.z;
                As[kk + 3][rowA] = v.w;
            }
        }
        // ---- load B tile (32 k x 128 co)
        {
#pragma unroll
            for (int r = 0; r < 4; r++) {
                const int kk = kB0 + r * 8;
                const float4 v = *(const float4*)(Wf +
                    (size_t)(kBase + kk) * 256 + coBase + c4 * 4);
                *(float4*)&Bs[kk][c4 * 4] = v;
            }
        }
        __syncthreads();

#pragma unroll
        for (int kk = 0; kk < 32; kk++) {
            float a[8], b[8];
            *(float4*)&a[0] = *(const float4*)&As[kk][ty * 4];
            *(float4*)&a[4] = *(const float4*)&As[kk][64 + ty * 4];
            *(float4*)&b[0] = *(const float4*)&Bs[kk][tx * 4];
            *(float4*)&b[4] = *(const float4*)&Bs[kk][64 + tx * 4];
#pragma unroll
            for (int i = 0; i < 8; i++)
#pragma unroll
                for (int j = 0; j < 8; j++)
                    acc[i][j] = fmaf(a[i], b[j], acc[i][j]);
        }
        __syncthreads();
    }

    // ---- store
#pragma unroll
    for (int i = 0; i < 8; i++) {
        const int mrow = mBase + ((i < 4) ? (ty * 4 + i) : (64 + ty * 4 + (i - 4)));
        float* dst = Z + (size_t)mrow * 256 + coBase;
        *(float4*)(dst + tx * 4)      = make_float4(acc[i][0], acc[i][1], acc[i][2], acc[i][3]);
        *(float4*)(dst + 64 + tx * 4) = make_float4(acc[i][4], acc[i][5], acc[i][6], acc[i][7]);
    }
}

// ---------------- LSTM cell + BN epilogue ----------------------------------
__device__ __forceinline__ float hsig(float x) {
    return fminf(fmaxf(0.2f * x + 0.5f, 0.f), 1.f);
}

__global__ void lstm_cell_kernel(int tstep,
                                 const float* __restrict__ z,
                                 const float* __restrict__ xz,
                                 const float* __restrict__ bias,
                                 const float* __restrict__ gamma,
                                 const float* __restrict__ beta,
                                 const float* __restrict__ mmean,
                                 const float* __restrict__ mvar,
                                 float* __restrict__ h,
                                 float* __restrict__ c,
                                 float* __restrict__ out) {
    const int idx = blockIdx.x * blockDim.x + threadIdx.x;   // 0 .. 4*4096*64-1
    const int f  = idx & 63;
    const int pg = idx >> 6;          // b*4096 + p
    const int b  = pg >> 12;
    const int p  = pg & 4095;
    const size_t nrow = (size_t)(b * 16 + tstep) * 4096 + p;

    const float* zr = z  + (size_t)pg * 256;
    const float* xr = xz + nrow * 256;

    const float zi = zr[f]       + xr[f]       + bias[f];
    const float zf = zr[f + 64]  + xr[f + 64]  + bias[f + 64];
    const float zg = zr[f + 128] + xr[f + 128] + bias[f + 128];
    const float zo = zr[f + 192] + xr[f + 192] + bias[f + 192];

    const float ig = hsig(zi);
    const float fg = hsig(zf);
    const float og = hsig(zo);

    const float cn = fg * c[idx] + ig * tanhf(zg);
    const float hn = og * tanhf(cn);
    c[idx] = cn;
    h[idx] = hn;

    const float sc = gamma[f] * rsqrtf(mvar[f] + 1e-3f);
    out[nrow * 64 + f] = (hn - mmean[f]) * sc + beta[f];
}

// ---------------- launch ----------------------------------------------------
extern "C" void kernel_launch(void* const* d_in, const int* in_sizes, int n_in,
                              void* d_out, int out_size) {
    const float* x     = (const float*)d_in[0];  // (4,16,128,128,32)
    const float* W     = (const float*)d_in[1];  // (3,3,32,256)
    const float* U     = (const float*)d_in[2];  // (3,3,64,256)
    const float* bias  = (const float*)d_in[3];  // (256,)
    const float* gamma = (const float*)d_in[4];  // (64,)
    const float* beta  = (const float*)d_in[5];
    const float* mmean = (const float*)d_in[6];
    const float* mvar  = (const float*)d_in[7];
    float* out = (float*)d_out;                  // (4,16,64,64,64)

    float *xz_p, *z_p, *h_p, *c_p;
    cudaGetSymbolAddress((void**)&xz_p, g_xz);
    cudaGetSymbolAddress((void**)&z_p,  g_z);
    cudaGetSymbolAddress((void**)&h_p,  g_h);
    cudaGetSymbolAddress((void**)&c_p,  g_c);

    // 1) zero LSTM state (deterministic per launch)
    const int stateN = 4 * 4096 * 64;
    zero_state_kernel<<<stateN / 256, 256>>>(h_p, c_p, stateN);

    // 2) input-to-gate conv for all 64 images: stride 2, pad_low 0, Cin 32
    {
        dim3 grid(64 * 4096 / 128, 2);   // (2048, 2)
        conv_gemm_kernel<2, 0, 32, 128, 64><<<grid, 256>>>(x, W, xz_p);
    }

    // 3) recurrent loop
    for (int t = 0; t < 16; ++t) {
        dim3 grid(4 * 4096 / 128, 2);    // (128, 2): stride 1, pad 1, Cin 64
        conv_gemm_kernel<1, 1, 64, 64, 64><<<grid, 256>>>(h_p, U, z_p);
        lstm_cell_kernel<<<stateN / 256, 256>>>(t, z_p, xz_p, bias, gamma, beta,
                                                mmean, mvar, h_p, c_p, out);
    }
}

// round 7
// speedup vs baseline: 2.0107x; 2.0107x over previous
#include <cuda_runtime.h>
#include <math.h>
#include <stdint.h>

// ================= scratch (device globals; no allocations) =================
__device__ float g_xz[(size_t)64 * 4096 * 256];   // input-conv gates (268 MB)
__device__ float g_h [(size_t)4 * 4096 * 64];
__device__ float g_h2[(size_t)4 * 4096 * 64];
__device__ float g_c [(size_t)4 * 4096 * 64];
__device__ float g_Wt[(size_t)9  * 256 * 32];     // W chunk-major [ch][co][kk]
__device__ float g_Ut[(size_t)18 * 256 * 32];

// ================= helpers ==================================================
__device__ __forceinline__ uint32_t f2tf32(float x) {
    uint32_t y;
    asm("cvt.rna.tf32.f32 %0, %1;" : "=r"(y) : "f"(x));
    return y;
}

__device__ __forceinline__ void mma_tf32(float* d, const uint32_t* a, const uint32_t* b) {
    asm volatile("mma.sync.aligned.m16n8k8.row.col.f32.tf32.tf32.f32 "
                 "{%0,%1,%2,%3}, {%4,%5,%6,%7}, {%8,%9}, {%0,%1,%2,%3};"
                 : "+f"(d[0]), "+f"(d[1]), "+f"(d[2]), "+f"(d[3])
                 : "r"(a[0]), "r"(a[1]), "r"(a[2]), "r"(a[3]),
                   "r"(b[0]), "r"(b[1]));
}

// swizzled smem index (floats): row-major rows of 32 floats, float4-group XOR row&7
__device__ __forceinline__ int swidx(int r, int c) {
    return (r << 5) + ((((c >> 2) ^ (r & 7)) << 2) | (c & 3));
}

__device__ __forceinline__ float hsig(float x) {
    return fminf(fmaxf(0.2f * x + 0.5f, 0.f), 1.f);
}

// smem layout in floats: stage s at s*12288 (A tile 128x32 @+0, B tile 256x32 @+4096)
static constexpr uint32_t SMEM_BYTES = 24576u * 4u;  // 98304 B

// ================= small kernels ============================================
__global__ void zero_state_kernel(float* __restrict__ h, float* __restrict__ c, int n) {
    int i = blockIdx.x * blockDim.x + threadIdx.x;
    if (i < n) { h[i] = 0.f; c[i] = 0.f; }
}

// Wt2[ch][co][kk] = Wsrc[(ch*32+kk)*256 + co]
__global__ void transpose_w_kernel(const float* __restrict__ Wsrc, float* __restrict__ Wt2, int total) {
    int idx = blockIdx.x * blockDim.x + threadIdx.x;
    if (idx >= total) return;
    int ch = idx >> 13;
    int r  = idx & 8191;
    int co = r >> 5, kk = r & 31;
    Wt2[idx] = Wsrc[((ch * 32 + kk) * 256) + co];
}

// ================= mma.sync implicit-GEMM conv (+ fused LSTM) ===============
// BM=128, BN=256, BK=32, 256 threads (8 warps, 2m x 4n), warp tile 64x64.
template<int STRIDE, int PAD, int CIN, int HIN, int HOUT, bool FUSED>
__global__ void __launch_bounds__(256, 1)
conv_mma(const float* __restrict__ X, const float* __restrict__ Wt2,
         float* __restrict__ Z, int tstep,
         const float* __restrict__ xz,
         const float* __restrict__ bias, const float* __restrict__ gamma,
         const float* __restrict__ beta, const float* __restrict__ mmean,
         const float* __restrict__ mvar,
         float* __restrict__ hbuf, float* __restrict__ cbuf,
         float* __restrict__ out) {
    extern __shared__ float smem[];
    __shared__ float s_bias[256], s_scale[64], s_beta[64], s_mm[64];

    const int t = threadIdx.x;
    if (FUSED) {
        s_bias[t] = bias[t];
        if (t < 64) {
            s_scale[t] = gamma[t] * rsqrtf(mvar[t] + 1e-3f);
            s_beta[t]  = beta[t];
            s_mm[t]    = mmean[t];
        }
    }

    const int wid = t >> 5, lane = t & 31;
    const int gid = lane >> 2, tg = lane & 3;
    const int wm = wid >> 2, wn = wid & 3;      // warp grid 2(m) x 4(n)
    const int mBase = blockIdx.x * 128;
    constexpr int NCH = 9 * CIN / 32;

    // ---- A staging geometry: thread t stages pixel rA, ci quarter q (16 floats)
    const int rA = t >> 1, q = t & 1;
    const int mA   = mBase + rA;
    const int nimg = mA / (HOUT * HOUT);
    const int remA = mA % (HOUT * HOUT);
    const int oy = remA / HOUT, ox = remA % HOUT;

    float d[4][8][4];
#pragma unroll
    for (int i = 0; i < 4; i++)
#pragma unroll
        for (int j = 0; j < 8; j++)
#pragma unroll
            for (int k = 0; k < 4; k++) d[i][j][k] = 0.f;

    float4 ar[4], br[8];

    auto gload = [&](int c) {
        const int tap   = (c * 32) / CIN;
        const int ciOff = (c * 32) % CIN + q * 16;
        const int ky = tap / 3, kx = tap % 3;
        const int iy = oy * STRIDE + ky - PAD;
        const int ix = ox * STRIDE + kx - PAD;
        const bool ok = (iy >= 0) & (iy < HIN) & (ix >= 0) & (ix < HIN);
        const float4* asrc = ok
            ? (const float4*)(X + (((size_t)nimg * HIN + iy) * HIN + ix) * CIN + ciOff)
            : nullptr;
#pragma unroll
        for (int j = 0; j < 4; j++)
            ar[j] = ok ? asrc[j] : make_float4(0.f, 0.f, 0.f, 0.f);
        const float4* bsrc = (const float4*)(Wt2 + (size_t)c * 8192);
#pragma unroll
        for (int j = 0; j < 8; j++)
            br[j] = bsrc[j * 256 + t];
    };

    auto sstore = [&](float* buf) {
#pragma unroll
        for (int j = 0; j < 4; j++) {
            const int g = q * 4 + j, sg = g ^ (rA & 7);
            uint4 u = make_uint4(f2tf32(ar[j].x), f2tf32(ar[j].y),
                                 f2tf32(ar[j].z), f2tf32(ar[j].w));
            *(uint4*)(buf + rA * 32 + sg * 4) = u;
        }
        float* bb = buf + 4096;
#pragma unroll
        for (int j = 0; j < 8; j++) {
            const int fidx = j * 256 + t, co = fidx >> 3, seg = fidx & 7;
            const int sg = seg ^ (co & 7);
            uint4 u = make_uint4(f2tf32(br[j].x), f2tf32(br[j].y),
                                 f2tf32(br[j].z), f2tf32(br[j].w));
            *(uint4*)(bb + co * 32 + sg * 4) = u;
        }
    };

    // ---- mainloop: double-buffered, one sync per chunk
    gload(0);
    sstore(smem);
    __syncthreads();
#pragma unroll 1
    for (int c = 0; c < NCH; ++c) {
        const float* cur = smem + (c & 1) * 12288;
        const uint32_t* As = (const uint32_t*)cur;
        const uint32_t* Bs = (const uint32_t*)(cur + 4096);
        if (c + 1 < NCH) gload(c + 1);
#pragma unroll
        for (int ks = 0; ks < 4; ks++) {
            uint32_t af[4][4], bf[8][2];
#pragma unroll
            for (int i = 0; i < 4; i++) {
                const int r0 = wm * 64 + i * 16 + gid;
                af[i][0] = As[swidx(r0,     ks * 8 + tg)];
                af[i][1] = As[swidx(r0 + 8, ks * 8 + tg)];
                af[i][2] = As[swidx(r0,     ks * 8 + tg + 4)];
                af[i][3] = As[swidx(r0 + 8, ks * 8 + tg + 4)];
            }
#pragma unroll
            for (int j = 0; j < 8; j++) {
                const int n0 = wn * 64 + j * 8 + gid;
                bf[j][0] = Bs[swidx(n0, ks * 8 + tg)];
                bf[j][1] = Bs[swidx(n0, ks * 8 + tg + 4)];
            }
#pragma unroll
            for (int i = 0; i < 4; i++)
#pragma unroll
                for (int j = 0; j < 8; j++)
                    mma_tf32(d[i][j], af[i], bf[j]);
        }
        if (c + 1 < NCH) sstore(smem + ((c + 1) & 1) * 12288);
        __syncthreads();
    }

    // ---- epilogue
    if (!FUSED) {
#pragma unroll
        for (int i = 0; i < 4; i++) {
            const int r0 = mBase + wm * 64 + i * 16 + gid;
#pragma unroll
            for (int j = 0; j < 8; j++) {
                const int col = wn * 64 + j * 8 + tg * 2;
                *(float2*)(Z + (size_t)r0 * 256 + col)       = make_float2(d[i][j][0], d[i][j][1]);
                *(float2*)(Z + (size_t)(r0 + 8) * 256 + col) = make_float2(d[i][j][2], d[i][j][3]);
            }
        }
    } else {
        float* zs = smem;  // 64 rows x 258 floats (reuses staging buffers)
#pragma unroll 1
        for (int half = 0; half < 2; half++) {
            __syncthreads();
            if (wm == half) {
#pragma unroll
                for (int i = 0; i < 4; i++) {
                    const int r0 = i * 16 + gid;
#pragma unroll
                    for (int j = 0; j < 8; j++) {
                        const int col = wn * 64 + j * 8 + tg * 2;
                        *(float2*)(zs + r0 * 258 + col)       = make_float2(d[i][j][0], d[i][j][1]);
                        *(float2*)(zs + (r0 + 8) * 258 + col) = make_float2(d[i][j][2], d[i][j][3]);
                    }
                }
            }
            __syncthreads();
#pragma unroll
            for (int it = 0; it < 16; it++) {
                const int idx = it * 256 + t;
                const int p = idx >> 6, f = idx & 63;
                const int m = mBase + half * 64 + p;
                const int b = m >> 12, pix = m & 4095;
                const size_t nrow = (size_t)(b * 16 + tstep) * 4096 + pix;
                const float* zr = zs + p * 258;
                const float* xr = xz + nrow * 256;
                const float zi = zr[f]       + xr[f]       + s_bias[f];
                const float zf = zr[64 + f]  + xr[64 + f]  + s_bias[64 + f];
                const float zg = zr[128 + f] + xr[128 + f] + s_bias[128 + f];
                const float zo = zr[192 + f] + xr[192 + f] + s_bias[192 + f];
                const float ig = hsig(zi), fg = hsig(zf), og = hsig(zo);
                const float cv = fg * cbuf[(size_t)m * 64 + f] + ig * tanhf(zg);
                const float hv = og * tanhf(cv);
                cbuf[(size_t)m * 64 + f] = cv;
                hbuf[(size_t)m * 64 + f] = hv;
                out[nrow * 64 + f] = (hv - s_mm[f]) * s_scale[f] + s_beta[f];
            }
        }
    }
}

// ================= launch ====================================================
extern "C" void kernel_launch(void* const* d_in, const int* in_sizes, int n_in,
                              void* d_out, int out_size) {
    const float* x     = (const float*)d_in[0];
    const float* W     = (const float*)d_in[1];
    const float* U     = (const float*)d_in[2];
    const float* bias  = (const float*)d_in[3];
    const float* gamma = (const float*)d_in[4];
    const float* beta  = (const float*)d_in[5];
    const float* mmean = (const float*)d_in[6];
    const float* mvar  = (const float*)d_in[7];
    float* out = (float*)d_out;

    float *xz_p, *h_p, *h2_p, *c_p, *wt_p, *ut_p;
    cudaGetSymbolAddress((void**)&xz_p, g_xz);
    cudaGetSymbolAddress((void**)&h_p,  g_h);
    cudaGetSymbolAddress((void**)&h2_p, g_h2);
    cudaGetSymbolAddress((void**)&c_p,  g_c);
    cudaGetSymbolAddress((void**)&wt_p, g_Wt);
    cudaGetSymbolAddress((void**)&ut_p, g_Ut);

    cudaFuncSetAttribute(conv_mma<2, 0, 32, 128, 64, false>,
                         cudaFuncAttributeMaxDynamicSharedMemorySize, SMEM_BYTES);
    cudaFuncSetAttribute(conv_mma<1, 1, 64, 64, 64, true>,
                         cudaFuncAttributeMaxDynamicSharedMemorySize, SMEM_BYTES);

    const int stateN = 4 * 4096 * 64;
    zero_state_kernel<<<stateN / 256, 256>>>(h_p, c_p, stateN);

    transpose_w_kernel<<<(9 * 8192 + 255) / 256, 256>>>(W, wt_p, 9 * 8192);
    transpose_w_kernel<<<(18 * 8192 + 255) / 256, 256>>>(U, ut_p, 18 * 8192);

    // input-to-gate conv: all 64 images (M = 262144 -> 2048 CTAs)
    conv_mma<2, 0, 32, 128, 64, false><<<2048, 256, SMEM_BYTES>>>(
        x, wt_p, xz_p, 0, nullptr, nullptr, nullptr, nullptr, nullptr, nullptr,
        nullptr, nullptr, nullptr);

    // recurrent loop with fused LSTM/BN epilogue (M = 16384 -> 128 CTAs, 1 wave)
    float* hin = h_p;
    float* hout = h2_p;
    for (int t = 0; t < 16; ++t) {
        conv_mma<1, 1, 64, 64, 64, true><<<128, 256, SMEM_BYTES>>>(
            hin, ut_p, nullptr, t, xz_p, bias, gamma, beta, mmean, mvar,
            hout, c_p, out);
        float* tmp = hin; hin = hout; hout = tmp;
    }
}

// round 12
// speedup vs baseline: 2.2024x; 1.0953x over previous
#include <cuda_runtime.h>
#include <math.h>
#include <stdint.h>

// ================= scratch (device globals; no allocations) =================
__device__ float g_xz[(size_t)64 * 4096 * 256];     // input-conv gates fp32 (268 MB)
__device__ float g_xp[(size_t)64 * 16384 * 32];     // x tf32, k-interleaved (134 MB)
__device__ float g_hp0[(size_t)4 * 4096 * 64];      // h tf32 k-interleaved
__device__ float g_hp1[(size_t)4 * 4096 * 64];
__device__ float g_c  [(size_t)4 * 4096 * 64];
__device__ float g_Wt[(size_t)9  * 256 * 32];       // W tf32 chunk-major interleaved
__device__ float g_Ut[(size_t)18 * 256 * 32];

// ================= helpers ==================================================
__device__ __forceinline__ uint32_t f2tf32(float x) {
    uint32_t y;
    asm("cvt.rna.tf32.f32 %0, %1;" : "=r"(y) : "f"(x));
    return y;
}
__device__ __forceinline__ uint32_t smem_u32(const void* p) {
    uint32_t a;
    asm("{ .reg .u64 t; cvta.to.shared.u64 t, %1; cvt.u32.u64 %0, t; }" : "=r"(a) : "l"(p));
    return a;
}
__device__ __forceinline__ void mma_tf32(float* d, const uint32_t* a, const uint32_t* b) {
    asm volatile("mma.sync.aligned.m16n8k8.row.col.f32.tf32.tf32.f32 "
                 "{%0,%1,%2,%3}, {%4,%5,%6,%7}, {%8,%9}, {%0,%1,%2,%3};"
                 : "+f"(d[0]), "+f"(d[1]), "+f"(d[2]), "+f"(d[3])
                 : "r"(a[0]), "r"(a[1]), "r"(a[2]), "r"(a[3]),
                   "r"(b[0]), "r"(b[1]));
}
#define CP_ASYNC(dst, src, sz) \
    asm volatile("cp.async.ca.shared.global [%0], [%1], 16, %2;" \
                 :: "r"(dst), "l"(src), "r"(sz) : "memory")
#define CP_COMMIT()  asm volatile("cp.async.commit_group;" ::: "memory")
#define CP_WAIT_1()  asm volatile("cp.async.wait_group 1;" ::: "memory")
#define CP_WAIT_0()  asm volatile("cp.async.wait_group 0;" ::: "memory")

__device__ __forceinline__ float hsig(float x) {
    return fminf(fmaxf(0.2f * x + 0.5f, 0.f), 1.f);
}

// k-interleave: position p in octet holds source k = (p&1)*4 + (p>>1)
__device__ __forceinline__ int perm_src(int pos) {        // pos in [0,32)
    return (pos & ~7) + ((pos & 1) * 4) + ((pos & 7) >> 1);
}
__device__ __forceinline__ int perm_dst(int f) {          // inverse, f in [0,64)
    return (f & ~7) + ((f & 3) * 2) + ((f >> 2) & 1);
}

// smem: 2 stages of 12288 floats (A 128x32 @+0, B 256x32 @+4096 floats)
static constexpr uint32_t SMEM_BYTES = 24576u * 4u;   // 98304 B

// ================= prep kernels =============================================
__global__ void zero_state_kernel(float* __restrict__ h, float* __restrict__ c, int n) {
    int i = blockIdx.x * blockDim.x + threadIdx.x;
    if (i < n) { h[i] = 0.f; c[i] = 0.f; }
}

__global__ void convert_x_kernel(const float* __restrict__ x, float* __restrict__ xp, int total) {
    int idx = blockIdx.x * blockDim.x + threadIdx.x;
    if (idx >= total) return;
    int pix = idx >> 5, pos = idx & 31;
    xp[idx] = __uint_as_float(f2tf32(x[pix * 32 + perm_src(pos)]));
}

// Wt2[ch][co][pos] = tf32(Wsrc[(ch*32 + perm_src(pos))*256 + co])
__global__ void transpose_w_kernel(const float* __restrict__ Wsrc, float* __restrict__ Wt2, int total) {
    int idx = blockIdx.x * blockDim.x + threadIdx.x;
    if (idx >= total) return;
    int ch = idx >> 13;
    int r  = idx & 8191;
    int co = r >> 5, pos = r & 31;
    Wt2[idx] = __uint_as_float(f2tf32(Wsrc[(ch * 32 + perm_src(pos)) * 256 + co]));
}

// ================= cp.async implicit-GEMM conv (+ fused LSTM) ===============
// BM=128, BN=256, BK=32; 512 threads = 16 warps (4m x 4n), warp tile 32x64.
template<int STRIDE, int PAD, int CIN, int HIN, int HOUT, bool FUSED>
__global__ void __launch_bounds__(512, 1)
conv_mma(const float* __restrict__ X, const float* __restrict__ Wt2,
         float* __restrict__ Z, int tstep,
         const float* __restrict__ xz,
         const float* __restrict__ bias, const float* __restrict__ gamma,
         const float* __restrict__ beta, const float* __restrict__ mmean,
         const float* __restrict__ mvar,
         float* __restrict__ hp_out, float* __restrict__ cbuf,
         float* __restrict__ out) {
    extern __shared__ float smem[];
    __shared__ float s_bias[256], s_scale[64], s_beta[64], s_mm[64];

    const int t = threadIdx.x;
    if (FUSED) {
        if (t < 256) s_bias[t] = bias[t];
        if (t < 64) {
            s_scale[t] = gamma[t] * rsqrtf(mvar[t] + 1e-3f);
            s_beta[t]  = beta[t];
            s_mm[t]    = mmean[t];
        }
    }

    const int wid = t >> 5, lane = t & 31;
    const int gid = lane >> 2, tg = lane & 3;
    const int wm = wid >> 2, wn = wid & 3;       // warp grid 4(m) x 4(n)
    const int mBase = blockIdx.x * 128;
    constexpr int NCH = 9 * CIN / 32;

    // ---- cp.async geometry (fixed per thread)
    const int gq = t & 7;                        // 16B quad within 32-float row
    const int r0A = t >> 3;                      // A rows r0A and r0A+64
    int nimg[2], oyv[2], oxv[2];
#pragma unroll
    for (int k = 0; k < 2; k++) {
        const int m = mBase + r0A + k * 64;
        nimg[k] = m / (HOUT * HOUT);
        const int rem = m % (HOUT * HOUT);
        oyv[k] = rem / HOUT; oxv[k] = rem % HOUT;
    }
    const uint32_t sbase = smem_u32(smem);
    uint32_t aDst[2], bDst[4];
#pragma unroll
    for (int k = 0; k < 2; k++) {
        const int r = r0A + k * 64;
        aDst[k] = sbase + r * 128 + ((gq ^ (r & 7)) << 4);
    }
#pragma unroll
    for (int k = 0; k < 4; k++) {
        const int co = (t >> 3) + k * 64;
        bDst[k] = sbase + 16384 + co * 128 + ((gq ^ (co & 7)) << 4);
    }

    auto issue = [&](int c, int s) {
        const int tap   = (c * 32) / CIN;
        const int ciOff = (c * 32) % CIN;
        const int ky = tap / 3, kx = tap % 3;
        const uint32_t so = (uint32_t)s * 49152u;
#pragma unroll
        for (int k = 0; k < 2; k++) {
            const int iy = oyv[k] * STRIDE + ky - PAD;
            const int ix = oxv[k] * STRIDE + kx - PAD;
            const bool ok = (iy >= 0) & (iy < HIN) & (ix >= 0) & (ix < HIN);
            const float* src = ok
                ? X + (((size_t)nimg[k] * HIN + iy) * HIN + ix) * CIN + ciOff + gq * 4
                : X;
            CP_ASYNC(aDst[k] + so, src, ok ? 16 : 0);
        }
        const float* bsrc = Wt2 + (size_t)c * 8192 + (t >> 3) * 32 + gq * 4;
#pragma unroll
        for (int k = 0; k < 4; k++)
            CP_ASYNC(bDst[k] + so, bsrc + k * 2048, 16);
        CP_COMMIT();
    };

    float d[2][8][4];
#pragma unroll
    for (int i = 0; i < 2; i++)
#pragma unroll
        for (int j = 0; j < 8; j++)
#pragma unroll
            for (int k = 0; k < 4; k++) d[i][j][k] = 0.f;

    // ---- mainloop
    issue(0, 0);
#pragma unroll 1
    for (int c = 0; c < NCH; ++c) {
        if (c + 1 < NCH) { issue(c + 1, (c + 1) & 1); CP_WAIT_1(); }
        else             { CP_WAIT_0(); }
        __syncthreads();
        const float* cur = smem + (c & 1) * 12288;
        const float* Bs  = cur + 4096;
#pragma unroll
        for (int ks = 0; ks < 4; ks++) {
            const int gcol = ks * 2 + (tg >> 1);
            const int fo = (tg & 1) * 2;
            uint32_t af[2][4];
#pragma unroll
            for (int i = 0; i < 2; i++) {
                const int ra = wm * 32 + i * 16 + gid;
                const int rb = ra + 8;
                float2 lo = *(const float2*)(cur + ra * 32 + ((gcol ^ (ra & 7)) << 2) + fo);
                float2 hi = *(const float2*)(cur + rb * 32 + ((gcol ^ (rb & 7)) << 2) + fo);
                af[i][0] = __float_as_uint(lo.x);
                af[i][1] = __float_as_uint(hi.x);
                af[i][2] = __float_as_uint(lo.y);
                af[i][3] = __float_as_uint(hi.y);
            }
            uint32_t bf[8][2];
#pragma unroll
            for (int j = 0; j < 8; j++) {
                const int n0 = wn * 64 + j * 8 + gid;
                float2 v = *(const float2*)(Bs + n0 * 32 + ((gcol ^ (n0 & 7)) << 2) + fo);
                bf[j][0] = __float_as_uint(v.x);
                bf[j][1] = __float_as_uint(v.y);
            }
#pragma unroll
            for (int i = 0; i < 2; i++)
#pragma unroll
                for (int j = 0; j < 8; j++)
                    mma_tf32(d[i][j], af[i], bf[j]);
        }
        __syncthreads();
    }

    // ---- epilogue
    if (!FUSED) {
#pragma unroll
        for (int i = 0; i < 2; i++) {
            const int r0 = mBase + wm * 32 + i * 16 + gid;
#pragma unroll
            for (int j = 0; j < 8; j++) {
                const int col = wn * 64 + j * 8 + tg * 2;
                *(float2*)(Z + (size_t)r0 * 256 + col)       = make_float2(d[i][j][0], d[i][j][1]);
                *(float2*)(Z + (size_t)(r0 + 8) * 256 + col) = make_float2(d[i][j][2], d[i][j][3]);
            }
        }
    } else {
        float* zs = smem;   // 64 rows x 258 floats
#pragma unroll 1
        for (int half = 0; half < 2; half++) {
            __syncthreads();
            if ((wm >> 1) == half) {
#pragma unroll
                for (int i = 0; i < 2; i++) {
                    const int r0 = (wm & 1) * 32 + i * 16 + gid;
#pragma unroll
                    for (int j = 0; j < 8; j++) {
                        const int col = wn * 64 + j * 8 + tg * 2;
                        *(float2*)(zs + r0 * 258 + col)       = make_float2(d[i][j][0], d[i][j][1]);
                        *(float2*)(zs + (r0 + 8) * 258 + col) = make_float2(d[i][j][2], d[i][j][3]);
                    }
                }
            }
            __syncthreads();
#pragma unroll
            for (int it = 0; it < 8; it++) {
                const int idx = it * 512 + t;
                const int p = idx >> 6, f = idx & 63;
                const int m = mBase + half * 64 + p;
                const int b = m >> 12, pix = m & 4095;
                const size_t nrow = (size_t)(b * 16 + tstep) * 4096 + pix;
                const float* zr = zs + p * 258;
                const float* xr = xz + nrow * 256;
                const float zi = zr[f]       + xr[f]       + s_bias[f];
                const float zf = zr[64 + f]  + xr[64 + f]  + s_bias[64 + f];
                const float zg = zr[128 + f] + xr[128 + f] + s_bias[128 + f];
                const float zo = zr[192 + f] + xr[192 + f] + s_bias[192 + f];
                const float ig = hsig(zi), fg = hsig(zf), og = hsig(zo);
                const float cv = fg * cbuf[(size_t)m * 64 + f] + ig * tanhf(zg);
                const float hv = og * tanhf(cv);
                cbuf[(size_t)m * 64 + f] = cv;
                hp_out[(size_t)m * 64 + perm_dst(f)] = __uint_as_float(f2tf32(hv));
                out[nrow * 64 + f] = (hv - s_mm[f]) * s_scale[f] + s_beta[f];
            }
        }
    }
}

// ================= launch ====================================================
extern "C" void kernel_launch(void* const* d_in, const int* in_sizes, int n_in,
                              void* d_out, int out_size) {
    const float* x     = (const float*)d_in[0];
    const float* W     = (const float*)d_in[1];
    const float* U     = (const float*)d_in[2];
    const float* bias  = (const float*)d_in[3];
    const float* gamma = (const float*)d_in[4];
    const float* beta  = (const float*)d_in[5];
    const float* mmean = (const float*)d_in[6];
    const float* mvar  = (const float*)d_in[7];
    float* out = (float*)d_out;

    float *xz_p, *xp_p, *hp0, *hp1, *c_p, *wt_p, *ut_p;
    cudaGetSymbolAddress((void**)&xz_p, g_xz);
    cudaGetSymbolAddress((void**)&xp_p, g_xp);
    cudaGetSymbolAddress((void**)&hp0,  g_hp0);
    cudaGetSymbolAddress((void**)&hp1,  g_hp1);
    cudaGetSymbolAddress((void**)&c_p,  g_c);
    cudaGetSymbolAddress((void**)&wt_p, g_Wt);
    cudaGetSymbolAddress((void**)&ut_p, g_Ut);

    cudaFuncSetAttribute(conv_mma<2, 0, 32, 128, 64, false>,
                         cudaFuncAttributeMaxDynamicSharedMemorySize, SMEM_BYTES);
    cudaFuncSetAttribute(conv_mma<1, 1, 64, 64, 64, true>,
                         cudaFuncAttributeMaxDynamicSharedMemorySize, SMEM_BYTES);

    const int stateN = 4 * 4096 * 64;
    zero_state_kernel<<<stateN / 256, 256>>>(hp0, c_p, stateN);

    const int xN = 64 * 16384 * 32;
    convert_x_kernel<<<xN / 512, 512>>>(x, xp_p, xN);
    transpose_w_kernel<<<(9 * 8192 + 255) / 256, 256>>>(W, wt_p, 9 * 8192);
    transpose_w_kernel<<<(18 * 8192 + 255) / 256, 256>>>(U, ut_p, 18 * 8192);

    // input-to-gate conv: all 64 images (M = 262144 -> 2048 CTAs)
    conv_mma<2, 0, 32, 128, 64, false><<<2048, 512, SMEM_BYTES>>>(
        xp_p, wt_p, xz_p, 0, nullptr, nullptr, nullptr, nullptr, nullptr, nullptr,
        nullptr, nullptr, nullptr);

    // recurrent loop with fused LSTM/BN epilogue (M = 16384 -> 128 CTAs)
    float* hin = hp0;
    float* hout = hp1;
    for (int t = 0; t < 16; ++t) {
        conv_mma<1, 1, 64, 64, 64, true><<<128, 512, SMEM_BYTES>>>(
            hin, ut_p, nullptr, t, xz_p, bias, gamma, beta, mmean, mvar,
            hout, c_p, out);
        float* tmp = hin; hin = hout; hout = tmp;
    }
}